// round 1
// baseline (speedup 1.0000x reference)
#include <cuda_runtime.h>
#include <math.h>

// Problem constants
#define NB 4
#define NQ 1024
#define NK 1024
#define ND 256
#define NH 8
#define NC 32
#define NM (NB*NQ)          // 4096 rows for q-side GEMMs
#define HC (NH*NC)          // 256

// Scratch (device globals: no allocation allowed)
__device__ float g_q[NB*NH*NQ*NC];   // [B,H,Q,C], pre-scaled by 1/sqrt(C)
__device__ float g_k[NB*NH*NK*NC];   // [B,H,K,C]
__device__ float g_v[NB*NH*NK*NC];   // [B,H,K,C]
__device__ float g_g[NM*HC];         // sigmoid gate [B*Q, H*C]
__device__ float g_o[NM*HC];         // attention output [B,Q,H*C]

// ---------------------------------------------------------------------------
// Kernel 1: all four projections. grid = (N/128, M/64, 4), block = 256.
// Tile 64x128, micro 4x8 per thread. mode: 0=q,1=k,2=v,3=gate
// ---------------------------------------------------------------------------
__global__ __launch_bounds__(256) void proj_kernel(
    const float* __restrict__ q_x, const float* __restrict__ kv_x,
    const float* __restrict__ wq, const float* __restrict__ wk,
    const float* __restrict__ wv, const float* __restrict__ wg,
    const float* __restrict__ bg)
{
    const int mode = blockIdx.z;
    const float* A = (mode == 1 || mode == 2) ? kv_x : q_x;
    const float* W = (mode == 0) ? wq : (mode == 1) ? wk : (mode == 2) ? wv : wg;

    __shared__ float Ast[16][65];   // [kk][row]  (A transposed)
    __shared__ float Bs[16][129];   // [kk][col]

    const int t  = threadIdx.x;
    const int tx = t & 15;
    const int ty = t >> 4;
    const int m0 = blockIdx.y * 64;
    const int n0 = blockIdx.x * 128;

    float acc[4][8];
#pragma unroll
    for (int i = 0; i < 4; i++)
#pragma unroll
        for (int j = 0; j < 8; j++) acc[i][j] = 0.f;

    for (int k0 = 0; k0 < ND; k0 += 16) {
        // load A tile (64 rows x 16 k) transposed
        {
            const int kk = t & 15;
            const int rb = t >> 4;
#pragma unroll
            for (int u = 0; u < 4; u++) {
                const int r = rb + 16 * u;
                Ast[kk][r] = A[(m0 + r) * ND + k0 + kk];
            }
        }
        // load B tile (16 k x 128 cols)
        {
            const int c  = t & 127;
            const int kb = t >> 7;
#pragma unroll
            for (int u = 0; u < 8; u++) {
                const int kk = kb + 2 * u;
                Bs[kk][c] = W[(k0 + kk) * HC + n0 + c];
            }
        }
        __syncthreads();
#pragma unroll
        for (int kk = 0; kk < 16; kk++) {
            float a[4], b[8];
#pragma unroll
            for (int i = 0; i < 4; i++) a[i] = Ast[kk][i * 16 + ty];
#pragma unroll
            for (int j = 0; j < 8; j++) b[j] = Bs[kk][j * 16 + tx];
#pragma unroll
            for (int i = 0; i < 4; i++)
#pragma unroll
                for (int j = 0; j < 8; j++) acc[i][j] += a[i] * b[j];
        }
        __syncthreads();
    }

    const float qscale = 0.17677669529663687f;  // 1/sqrt(32)
#pragma unroll
    for (int i = 0; i < 4; i++) {
        const int m = m0 + i * 16 + ty;
        const int b = m >> 10;          // / 1024
        const int l = m & 1023;
#pragma unroll
        for (int j = 0; j < 8; j++) {
            const int n = n0 + j * 16 + tx;
            const int h = n >> 5;       // / 32
            const int c = n & 31;
            float v = acc[i][j];
            if (mode == 0) {
                g_q[(((b * NH + h) * NQ) + l) * NC + c] = v * qscale;
            } else if (mode == 1) {
                g_k[(((b * NH + h) * NK) + l) * NC + c] = v;
            } else if (mode == 2) {
                g_v[(((b * NH + h) * NK) + l) * NC + c] = v;
            } else {
                g_g[m * HC + n] = 1.f / (1.f + __expf(-(v + bg[n])));
            }
        }
    }
}

// ---------------------------------------------------------------------------
// Kernel 2: flash attention per (b,h). grid = (Q/64, B*H), block = 256.
// Q-tile 64, K-tile 128, online softmax, P via smem.
// ---------------------------------------------------------------------------
#define QPAD 33
#define KPAD 33
#define PPAD 129

extern __shared__ float sm_attn[];

__global__ __launch_bounds__(256) void attn_kernel(
    const float* __restrict__ bias_mask,   // [B, K]
    const float* __restrict__ bias_pair)   // [B, H, Q, K]
{
    float* qs = sm_attn;                   // 64 x 33
    float* ks = qs + 64 * QPAD;            // 128 x 33
    float* vs = ks + 128 * KPAD;           // 128 x 33
    float* ps = vs + 128 * KPAD;           // 64 x 129

    const int t  = threadIdx.x;
    const int tx = t & 15;
    const int ty = t >> 4;
    const int bh = blockIdx.y;
    const int b  = bh >> 3;
    const int q0 = blockIdx.x * 64;

    const float* qptr = g_q + ((size_t)bh * NQ + q0) * NC;
    const float* kbas = g_k + (size_t)bh * NK * NC;
    const float* vbas = g_v + (size_t)bh * NK * NC;
    const float* bmrow = bias_mask + b * NK;
    const float* bprow = bias_pair + ((size_t)bh * NQ + q0) * NK;

    // load q tile (64x32)
#pragma unroll
    for (int u = 0; u < 8; u++) {
        const int e = t + 256 * u;
        const int r = e >> 5, c = e & 31;
        qs[r * QPAD + c] = qptr[r * NC + c];
    }

    float m_i[4], l_i[4], o[4][2];
#pragma unroll
    for (int i = 0; i < 4; i++) {
        m_i[i] = -1e30f; l_i[i] = 0.f; o[i][0] = 0.f; o[i][1] = 0.f;
    }

    for (int kb = 0; kb < 8; kb++) {
        __syncthreads();   // prior AV consumers done before overwriting ks/vs/ps
        // load K,V tiles (128x32 each)
#pragma unroll
        for (int u = 0; u < 16; u++) {
            const int e = t + 256 * u;
            const int r = e >> 5, c = e & 31;
            ks[r * KPAD + c] = kbas[(kb * 128 + r) * NC + c];
            vs[r * KPAD + c] = vbas[(kb * 128 + r) * NC + c];
        }
        __syncthreads();

        // S = q @ k^T  (64x128), thread owns rows i*16+ty, cols j*16+tx
        float s[4][8];
#pragma unroll
        for (int i = 0; i < 4; i++)
#pragma unroll
            for (int j = 0; j < 8; j++) s[i][j] = 0.f;
#pragma unroll
        for (int c = 0; c < NC; c++) {
            float a[4], bb[8];
#pragma unroll
            for (int i = 0; i < 4; i++) a[i] = qs[(i * 16 + ty) * QPAD + c];
#pragma unroll
            for (int j = 0; j < 8; j++) bb[j] = ks[(j * 16 + tx) * KPAD + c];
#pragma unroll
            for (int i = 0; i < 4; i++)
#pragma unroll
                for (int j = 0; j < 8; j++) s[i][j] += a[i] * bb[j];
        }

        // biases
#pragma unroll
        for (int i = 0; i < 4; i++) {
            const int qg = q0 + i * 16 + ty;
            const float* bp = bprow + ((size_t)(i * 16 + ty)) * NK + kb * 128;
            (void)qg;
#pragma unroll
            for (int j = 0; j < 8; j++) {
                const int kl = j * 16 + tx;
                s[i][j] += bmrow[kb * 128 + kl] + bp[kl];
            }
        }

        // online softmax per row group
#pragma unroll
        for (int i = 0; i < 4; i++) {
            float mx = s[i][0];
#pragma unroll
            for (int j = 1; j < 8; j++) mx = fmaxf(mx, s[i][j]);
#pragma unroll
            for (int off = 1; off < 16; off <<= 1)
                mx = fmaxf(mx, __shfl_xor_sync(0xffffffffu, mx, off));
            const float mnew  = fmaxf(m_i[i], mx);
            const float alpha = __expf(m_i[i] - mnew);
            float sum = 0.f;
#pragma unroll
            for (int j = 0; j < 8; j++) {
                const float p = __expf(s[i][j] - mnew);
                s[i][j] = p;
                sum += p;
            }
#pragma unroll
            for (int off = 1; off < 16; off <<= 1)
                sum += __shfl_xor_sync(0xffffffffu, sum, off);
            l_i[i] = l_i[i] * alpha + sum;
            m_i[i] = mnew;
            o[i][0] *= alpha;
            o[i][1] *= alpha;
#pragma unroll
            for (int j = 0; j < 8; j++)
                ps[(i * 16 + ty) * PPAD + j * 16 + tx] = s[i][j];
        }
        __syncthreads();

        // O += P @ V : thread owns rows i*16+ty, cols tx*2 + {0,1}
#pragma unroll 4
        for (int k = 0; k < 128; k++) {
            const float v0 = vs[k * KPAD + tx * 2];
            const float v1 = vs[k * KPAD + tx * 2 + 1];
            float p;
#pragma unroll
            for (int i = 0; i < 4; i++) {
                p = ps[(i * 16 + ty) * PPAD + k];
                o[i][0] += p * v0;
                o[i][1] += p * v1;
            }
        }
    }

    // epilogue: normalize, write to [B, Q, H*C]
    const int h = bh & 7;
#pragma unroll
    for (int i = 0; i < 4; i++) {
        const int qg  = q0 + i * 16 + ty;
        const float inv = 1.f / l_i[i];
        const size_t base = (((size_t)b * NQ + qg) * NH + h) * NC + tx * 2;
        g_o[base]     = o[i][0] * inv;
        g_o[base + 1] = o[i][1] * inv;
    }
}

// ---------------------------------------------------------------------------
// Kernel 3: out = (o * g) @ wo + bo. grid = (N/128, M/64), block = 256.
// ---------------------------------------------------------------------------
__global__ __launch_bounds__(256) void out_kernel(
    const float* __restrict__ wo, const float* __restrict__ bo,
    float* __restrict__ out)
{
    __shared__ float Ast[16][65];
    __shared__ float Bs[16][129];

    const int t  = threadIdx.x;
    const int tx = t & 15;
    const int ty = t >> 4;
    const int m0 = blockIdx.y * 64;
    const int n0 = blockIdx.x * 128;

    float acc[4][8];
#pragma unroll
    for (int i = 0; i < 4; i++)
#pragma unroll
        for (int j = 0; j < 8; j++) acc[i][j] = 0.f;

    for (int k0 = 0; k0 < HC; k0 += 16) {
        {
            const int kk = t & 15;
            const int rb = t >> 4;
#pragma unroll
            for (int u = 0; u < 4; u++) {
                const int r = rb + 16 * u;
                const int idx = (m0 + r) * HC + k0 + kk;
                Ast[kk][r] = g_o[idx] * g_g[idx];
            }
        }
        {
            const int c  = t & 127;
            const int kb = t >> 7;
#pragma unroll
            for (int u = 0; u < 8; u++) {
                const int kk = kb + 2 * u;
                Bs[kk][c] = wo[(k0 + kk) * ND + n0 + c];
            }
        }
        __syncthreads();
#pragma unroll
        for (int kk = 0; kk < 16; kk++) {
            float a[4], b[8];
#pragma unroll
            for (int i = 0; i < 4; i++) a[i] = Ast[kk][i * 16 + ty];
#pragma unroll
            for (int j = 0; j < 8; j++) b[j] = Bs[kk][j * 16 + tx];
#pragma unroll
            for (int i = 0; i < 4; i++)
#pragma unroll
                for (int j = 0; j < 8; j++) acc[i][j] += a[i] * b[j];
        }
        __syncthreads();
    }

#pragma unroll
    for (int i = 0; i < 4; i++) {
        const int m = m0 + i * 16 + ty;
#pragma unroll
        for (int j = 0; j < 8; j++) {
            const int n = n0 + j * 16 + tx;
            out[m * ND + n] = acc[i][j] + bo[n];
        }
    }
}

// ---------------------------------------------------------------------------
// Launch
// ---------------------------------------------------------------------------
extern "C" void kernel_launch(void* const* d_in, const int* in_sizes, int n_in,
                              void* d_out, int out_size)
{
    const float* q_x       = (const float*)d_in[0];
    const float* kv_x      = (const float*)d_in[1];
    const float* bias_mask = (const float*)d_in[2];
    const float* bias_pair = (const float*)d_in[3];
    const float* wq        = (const float*)d_in[4];
    const float* wk        = (const float*)d_in[5];
    const float* wv        = (const float*)d_in[6];
    const float* wg        = (const float*)d_in[7];
    const float* bg        = (const float*)d_in[8];
    const float* wo        = (const float*)d_in[9];
    const float* bo        = (const float*)d_in[10];
    float* out             = (float*)d_out;

    // projections: q, k, v, gate
    {
        dim3 grid(HC / 128, NM / 64, 4);
        proj_kernel<<<grid, 256>>>(q_x, kv_x, wq, wk, wv, wg, bg);
    }
    // flash attention
    {
        const int smem = (64 * QPAD + 2 * 128 * KPAD + 64 * PPAD) * (int)sizeof(float);
        cudaFuncSetAttribute(attn_kernel, cudaFuncAttributeMaxDynamicSharedMemorySize, smem);
        dim3 grid(NQ / 64, NB * NH);
        attn_kernel<<<grid, 256, smem>>>(bias_mask, bias_pair);
    }
    // gated output projection
    {
        dim3 grid(ND / 128, NM / 64);
        out_kernel<<<grid, 256>>>(wo, bo, out);
    }
}

// round 4
// speedup vs baseline: 1.5849x; 1.5849x over previous
#include <cuda_runtime.h>
#include <math.h>
#include <stdint.h>

// Problem constants
#define NB 4
#define NQ 1024
#define NK 1024
#define ND 256
#define NH 8
#define NC 32
#define NM (NB*NQ)
#define HC (NH*NC)

// Scratch (device globals)
__device__ float g_q[NB*NH*NQ*NC];   // [B,H,Q,C], pre-scaled by 1/sqrt(C)
__device__ float g_k[NB*NH*NK*NC];   // [B,H,K,C]
__device__ float g_v[NB*NH*NK*NC];   // [B,H,K,C]
__device__ float g_g[NM*HC];         // sigmoid gate
__device__ float g_o[NM*HC];         // attention output

// ---------------------------------------------------------------------------
// TF32 helpers: split x into hi (tf32) + lo (tf32 of residual); 3-mma product
// ---------------------------------------------------------------------------
__device__ __forceinline__ uint32_t f2tf(float f) {
    uint32_t u;
    asm("cvt.rna.tf32.f32 %0, %1;" : "=r"(u) : "f"(f));
    return u;
}
__device__ __forceinline__ void tfsplit(float x, uint32_t& hi, uint32_t& lo) {
    hi = f2tf(x);
    lo = f2tf(x - __uint_as_float(hi));
}
__device__ __forceinline__ void mma_tf32(float* d,
                                         uint32_t a0, uint32_t a1, uint32_t a2, uint32_t a3,
                                         uint32_t b0, uint32_t b1) {
    asm volatile(
        "mma.sync.aligned.m16n8k8.row.col.f32.tf32.tf32.f32 "
        "{%0,%1,%2,%3}, {%4,%5,%6,%7}, {%8,%9}, {%0,%1,%2,%3};\n"
        : "+f"(d[0]), "+f"(d[1]), "+f"(d[2]), "+f"(d[3])
        : "r"(a0), "r"(a1), "r"(a2), "r"(a3), "r"(b0), "r"(b1));
}

#define APAD 36
#define BPAD 132
#define KVPAD 36
#define PPAD  68

extern __shared__ float smp[];

// ---------------------------------------------------------------------------
// Kernel 1: projections, 3xTF32. grid=(2, 32, 4), block=256, dyn smem.
// Block tile 128x128, k-step 32. Warp tile 32x64. mode: 0=q,1=k,2=v,3=gate
// ---------------------------------------------------------------------------
__global__ __launch_bounds__(256) void proj_kernel(
    const float* __restrict__ q_x, const float* __restrict__ kv_x,
    const float* __restrict__ wq, const float* __restrict__ wk,
    const float* __restrict__ wv, const float* __restrict__ wg,
    const float* __restrict__ bg)
{
    const int mode = blockIdx.z;
    const float* A = (mode == 1 || mode == 2) ? kv_x : q_x;
    const float* W = (mode == 0) ? wq : (mode == 1) ? wk : (mode == 2) ? wv : wg;

    float* Ash = smp;                    // [128][APAD]
    float* Asl = Ash + 128 * APAD;
    float* Bsh = Asl + 128 * APAD;       // [32][BPAD]
    float* Bsl = Bsh + 32 * BPAD;

    const int tid  = threadIdx.x;
    const int lane = tid & 31;
    const int wid  = tid >> 5;
    const int gid  = lane >> 2;
    const int m4   = lane & 3;
    const int wm   = wid & 3;
    const int wn   = wid >> 2;
    const int m0   = blockIdx.y * 128;
    const int n0   = blockIdx.x * 128;

    float acc[2][8][4];
#pragma unroll
    for (int mt = 0; mt < 2; mt++)
#pragma unroll
        for (int nt = 0; nt < 8; nt++)
#pragma unroll
            for (int r = 0; r < 4; r++) acc[mt][nt][r] = 0.f;

    for (int k0 = 0; k0 < ND; k0 += 32) {
        __syncthreads();
#pragma unroll
        for (int u = 0; u < 4; u++) {
            const int e  = tid + 256 * u;
            const int r  = e >> 3;
            const int c4 = (e & 7) * 4;
            float4 va = *(const float4*)(A + (size_t)(m0 + r) * ND + k0 + c4);
            uint32_t h0,l0,h1,l1,h2,l2,h3,l3;
            tfsplit(va.x, h0, l0); tfsplit(va.y, h1, l1);
            tfsplit(va.z, h2, l2); tfsplit(va.w, h3, l3);
            *(uint4*)(Ash + r * APAD + c4) = make_uint4(h0,h1,h2,h3);
            *(uint4*)(Asl + r * APAD + c4) = make_uint4(l0,l1,l2,l3);
        }
#pragma unroll
        for (int u = 0; u < 4; u++) {
            const int e  = tid + 256 * u;
            const int r  = e >> 5;
            const int c4 = (e & 31) * 4;
            float4 vb = *(const float4*)(W + (size_t)(k0 + r) * HC + n0 + c4);
            uint32_t h0,l0,h1,l1,h2,l2,h3,l3;
            tfsplit(vb.x, h0, l0); tfsplit(vb.y, h1, l1);
            tfsplit(vb.z, h2, l2); tfsplit(vb.w, h3, l3);
            *(uint4*)(Bsh + r * BPAD + c4) = make_uint4(h0,h1,h2,h3);
            *(uint4*)(Bsl + r * BPAD + c4) = make_uint4(l0,l1,l2,l3);
        }
        __syncthreads();

#pragma unroll
        for (int kc = 0; kc < 4; kc++) {
            uint32_t ah[2][4], al[2][4];
#pragma unroll
            for (int mt = 0; mt < 2; mt++) {
                const int rb = wm * 32 + mt * 16 + gid;
                ah[mt][0] = __float_as_uint(Ash[(rb)     * APAD + kc * 8 + m4]);
                ah[mt][1] = __float_as_uint(Ash[(rb + 8) * APAD + kc * 8 + m4]);
                ah[mt][2] = __float_as_uint(Ash[(rb)     * APAD + kc * 8 + m4 + 4]);
                ah[mt][3] = __float_as_uint(Ash[(rb + 8) * APAD + kc * 8 + m4 + 4]);
                al[mt][0] = __float_as_uint(Asl[(rb)     * APAD + kc * 8 + m4]);
                al[mt][1] = __float_as_uint(Asl[(rb + 8) * APAD + kc * 8 + m4]);
                al[mt][2] = __float_as_uint(Asl[(rb)     * APAD + kc * 8 + m4 + 4]);
                al[mt][3] = __float_as_uint(Asl[(rb + 8) * APAD + kc * 8 + m4 + 4]);
            }
#pragma unroll
            for (int nt = 0; nt < 8; nt++) {
                const int cb = wn * 64 + nt * 8 + gid;
                uint32_t bh0 = __float_as_uint(Bsh[(kc * 8 + m4)     * BPAD + cb]);
                uint32_t bh1 = __float_as_uint(Bsh[(kc * 8 + m4 + 4) * BPAD + cb]);
                uint32_t bl0 = __float_as_uint(Bsl[(kc * 8 + m4)     * BPAD + cb]);
                uint32_t bl1 = __float_as_uint(Bsl[(kc * 8 + m4 + 4) * BPAD + cb]);
#pragma unroll
                for (int mt = 0; mt < 2; mt++) {
                    mma_tf32(acc[mt][nt], ah[mt][0], ah[mt][1], ah[mt][2], ah[mt][3], bh0, bh1);
                    mma_tf32(acc[mt][nt], ah[mt][0], ah[mt][1], ah[mt][2], ah[mt][3], bl0, bl1);
                    mma_tf32(acc[mt][nt], al[mt][0], al[mt][1], al[mt][2], al[mt][3], bh0, bh1);
                }
            }
        }
    }

    const float qscale = 0.17677669529663687f;  // 1/sqrt(32)
#pragma unroll
    for (int mt = 0; mt < 2; mt++) {
#pragma unroll
        for (int rr = 0; rr < 2; rr++) {
            const int row = m0 + wm * 32 + mt * 16 + gid + rr * 8;
            const int b   = row >> 10;
            const int l   = row & 1023;
#pragma unroll
            for (int nt = 0; nt < 8; nt++) {
                const int n = n0 + wn * 64 + nt * 8 + 2 * m4;
                const int h = n >> 5;
                const int c = n & 31;
                float v0 = acc[mt][nt][rr * 2 + 0];
                float v1 = acc[mt][nt][rr * 2 + 1];
                if (mode == 0) {
                    *(float2*)(g_q + ((((size_t)b * NH + h) * NQ) + l) * NC + c) =
                        make_float2(v0 * qscale, v1 * qscale);
                } else if (mode == 1) {
                    *(float2*)(g_k + ((((size_t)b * NH + h) * NK) + l) * NC + c) = make_float2(v0, v1);
                } else if (mode == 2) {
                    *(float2*)(g_v + ((((size_t)b * NH + h) * NK) + l) * NC + c) = make_float2(v0, v1);
                } else {
                    float s0 = 1.f / (1.f + __expf(-(v0 + bg[n])));
                    float s1 = 1.f / (1.f + __expf(-(v1 + bg[n + 1])));
                    *(float2*)(g_g + (size_t)row * HC + n) = make_float2(s0, s1);
                }
            }
        }
    }
}

// ---------------------------------------------------------------------------
// Kernel 2: flash attention, 3xTF32. grid=(8, 32), block=256, dyn smem.
// Q-tile 128 (warp owns 16 full rows), K-tile 64, online softmax.
// ---------------------------------------------------------------------------
__global__ __launch_bounds__(256) void attn_kernel(
    const float* __restrict__ bias_mask,   // [B, K]
    const float* __restrict__ bias_pair)   // [B, H, Q, K]
{
    float* ksh = smp;                      // [64][KVPAD]
    float* ksl = ksh + 64 * KVPAD;
    float* vsh = ksl + 64 * KVPAD;
    float* vsl = vsh + 64 * KVPAD;
    float* bms = vsl + 64 * KVPAD;         // [64]
    float* ps  = bms + 64;                 // [128][PPAD] fp32

    const int tid  = threadIdx.x;
    const int lane = tid & 31;
    const int wid  = tid >> 5;
    const int gid  = lane >> 2;
    const int m4   = lane & 3;
    const int bh   = blockIdx.y;
    const int b    = bh >> 3;
    const int h    = bh & 7;
    const int q0   = blockIdx.x * 128;
    const int r0   = q0 + wid * 16 + gid;

    // Q fragments hi/lo in registers
    uint32_t qh[4][4], ql[4][4];
    {
        const float* qb = g_q + (size_t)bh * NQ * NC;
#pragma unroll
        for (int kc = 0; kc < 4; kc++) {
            tfsplit(qb[(size_t)(r0)     * NC + kc * 8 + m4],     qh[kc][0], ql[kc][0]);
            tfsplit(qb[(size_t)(r0 + 8) * NC + kc * 8 + m4],     qh[kc][1], ql[kc][1]);
            tfsplit(qb[(size_t)(r0)     * NC + kc * 8 + m4 + 4], qh[kc][2], ql[kc][2]);
            tfsplit(qb[(size_t)(r0 + 8) * NC + kc * 8 + m4 + 4], qh[kc][3], ql[kc][3]);
        }
    }

    float m_i[2] = {-1e30f, -1e30f};
    float l_i[2] = {0.f, 0.f};
    float o[4][4];
#pragma unroll
    for (int nt = 0; nt < 4; nt++)
#pragma unroll
        for (int r = 0; r < 4; r++) o[nt][r] = 0.f;

    const float* kgb = g_k + (size_t)bh * NK * NC;
    const float* vgb = g_v + (size_t)bh * NK * NC;
    const float* bpb = bias_pair + ((size_t)bh * NQ + r0) * NK;
    const float* bmb = bias_mask + (size_t)b * NK;

    for (int kt = 0; kt < 16; kt++) {
        __syncthreads();
        {
            const float* kg = kgb + (size_t)kt * 64 * NC;
            const float* vg = vgb + (size_t)kt * 64 * NC;
#pragma unroll
            for (int u = 0; u < 8; u++) {
                const int e = tid + 256 * u;
                const int r = e >> 5, c = e & 31;
                uint32_t hk, lk, hv, lv;
                tfsplit(kg[r * NC + c], hk, lk);
                tfsplit(vg[r * NC + c], hv, lv);
                ksh[r * KVPAD + c] = __uint_as_float(hk);
                ksl[r * KVPAD + c] = __uint_as_float(lk);
                vsh[r * KVPAD + c] = __uint_as_float(hv);
                vsl[r * KVPAD + c] = __uint_as_float(lv);
            }
            if (tid < 64) bms[tid] = bmb[kt * 64 + tid];
        }
        __syncthreads();

        // S accumulators pre-loaded with biases
        float s[8][4];
        {
            const float* bp = bpb + kt * 64;
#pragma unroll
            for (int nt = 0; nt < 8; nt++) {
                const int c = nt * 8 + 2 * m4;
                const float bm0 = bms[c], bm1 = bms[c + 1];
                float2 p0 = *(const float2*)(bp + c);
                float2 p1 = *(const float2*)(bp + (size_t)8 * NK + c);
                s[nt][0] = p0.x + bm0; s[nt][1] = p0.y + bm1;
                s[nt][2] = p1.x + bm0; s[nt][3] = p1.y + bm1;
            }
        }
        // S += Q @ K^T  (3xTF32)
#pragma unroll
        for (int kc = 0; kc < 4; kc++) {
#pragma unroll
            for (int nt = 0; nt < 8; nt++) {
                const int cn = nt * 8 + gid;
                uint32_t bh0 = __float_as_uint(ksh[cn * KVPAD + kc * 8 + m4]);
                uint32_t bh1 = __float_as_uint(ksh[cn * KVPAD + kc * 8 + m4 + 4]);
                uint32_t bl0 = __float_as_uint(ksl[cn * KVPAD + kc * 8 + m4]);
                uint32_t bl1 = __float_as_uint(ksl[cn * KVPAD + kc * 8 + m4 + 4]);
                mma_tf32(s[nt], qh[kc][0], qh[kc][1], qh[kc][2], qh[kc][3], bh0, bh1);
                mma_tf32(s[nt], qh[kc][0], qh[kc][1], qh[kc][2], qh[kc][3], bl0, bl1);
                mma_tf32(s[nt], ql[kc][0], ql[kc][1], ql[kc][2], ql[kc][3], bh0, bh1);
            }
        }

        // online softmax (rows r0, r0+8); quad-local reduction
        float mx0 = -1e30f, mx1 = -1e30f;
#pragma unroll
        for (int nt = 0; nt < 8; nt++) {
            mx0 = fmaxf(mx0, fmaxf(s[nt][0], s[nt][1]));
            mx1 = fmaxf(mx1, fmaxf(s[nt][2], s[nt][3]));
        }
#pragma unroll
        for (int off = 1; off < 4; off <<= 1) {
            mx0 = fmaxf(mx0, __shfl_xor_sync(0xffffffffu, mx0, off));
            mx1 = fmaxf(mx1, __shfl_xor_sync(0xffffffffu, mx1, off));
        }
        const float mn0 = fmaxf(m_i[0], mx0);
        const float mn1 = fmaxf(m_i[1], mx1);
        const float al0 = __expf(m_i[0] - mn0);
        const float al1 = __expf(m_i[1] - mn1);
        float sum0 = 0.f, sum1 = 0.f;
        {
            float* p0 = ps + (size_t)(wid * 16 + gid)     * PPAD;
            float* p1 = ps + (size_t)(wid * 16 + gid + 8) * PPAD;
#pragma unroll
            for (int nt = 0; nt < 8; nt++) {
                const int c = nt * 8 + 2 * m4;
                float e0 = __expf(s[nt][0] - mn0);
                float e1 = __expf(s[nt][1] - mn0);
                float e2 = __expf(s[nt][2] - mn1);
                float e3 = __expf(s[nt][3] - mn1);
                sum0 += e0 + e1;
                sum1 += e2 + e3;
                p0[c] = e0; p0[c + 1] = e1;
                p1[c] = e2; p1[c + 1] = e3;
            }
        }
#pragma unroll
        for (int off = 1; off < 4; off <<= 1) {
            sum0 += __shfl_xor_sync(0xffffffffu, sum0, off);
            sum1 += __shfl_xor_sync(0xffffffffu, sum1, off);
        }
        l_i[0] = l_i[0] * al0 + sum0;
        l_i[1] = l_i[1] * al1 + sum1;
        m_i[0] = mn0; m_i[1] = mn1;
#pragma unroll
        for (int nt = 0; nt < 4; nt++) {
            o[nt][0] *= al0; o[nt][1] *= al0;
            o[nt][2] *= al1; o[nt][3] *= al1;
        }

        __syncwarp();
        // O += P @ V  (P split on the fly, V hi/lo from smem)
#pragma unroll
        for (int kc = 0; kc < 8; kc++) {
            const float* p0 = ps + (size_t)(wid * 16 + gid)     * PPAD + kc * 8;
            const float* p1 = ps + (size_t)(wid * 16 + gid + 8) * PPAD + kc * 8;
            uint32_t a0h,a0l,a1h,a1l,a2h,a2l,a3h,a3l;
            tfsplit(p0[m4],     a0h, a0l);
            tfsplit(p1[m4],     a1h, a1l);
            tfsplit(p0[m4 + 4], a2h, a2l);
            tfsplit(p1[m4 + 4], a3h, a3l);
#pragma unroll
            for (int nt = 0; nt < 4; nt++) {
                const int cn = nt * 8 + gid;
                uint32_t bh0 = __float_as_uint(vsh[(kc * 8 + m4)     * KVPAD + cn]);
                uint32_t bh1 = __float_as_uint(vsh[(kc * 8 + m4 + 4) * KVPAD + cn]);
                uint32_t bl0 = __float_as_uint(vsl[(kc * 8 + m4)     * KVPAD + cn]);
                uint32_t bl1 = __float_as_uint(vsl[(kc * 8 + m4 + 4) * KVPAD + cn]);
                mma_tf32(o[nt], a0h, a1h, a2h, a3h, bh0, bh1);
                mma_tf32(o[nt], a0h, a1h, a2h, a3h, bl0, bl1);
                mma_tf32(o[nt], a0l, a1l, a2l, a3l, bh0, bh1);
            }
        }
    }

    // epilogue
    const float inv0 = 1.f / l_i[0];
    const float inv1 = 1.f / l_i[1];
#pragma unroll
    for (int nt = 0; nt < 4; nt++) {
        const int c = nt * 8 + 2 * m4;
        *(float2*)(g_o + (((size_t)b * NQ + r0)     * NH + h) * NC + c) =
            make_float2(o[nt][0] * inv0, o[nt][1] * inv0);
        *(float2*)(g_o + (((size_t)b * NQ + r0 + 8) * NH + h) * NC + c) =
            make_float2(o[nt][2] * inv1, o[nt][3] * inv1);
    }
}

// ---------------------------------------------------------------------------
// Kernel 3: out = (o * g) @ wo + bo, 3xTF32. grid=(2, 32), block=256, dyn smem.
// ---------------------------------------------------------------------------
__global__ __launch_bounds__(256) void out_kernel(
    const float* __restrict__ wo, const float* __restrict__ bo,
    float* __restrict__ out)
{
    float* Ash = smp;
    float* Asl = Ash + 128 * APAD;
    float* Bsh = Asl + 128 * APAD;
    float* Bsl = Bsh + 32 * BPAD;

    const int tid  = threadIdx.x;
    const int lane = tid & 31;
    const int wid  = tid >> 5;
    const int gid  = lane >> 2;
    const int m4   = lane & 3;
    const int wm   = wid & 3;
    const int wn   = wid >> 2;
    const int m0   = blockIdx.y * 128;
    const int n0   = blockIdx.x * 128;

    float acc[2][8][4];
#pragma unroll
    for (int mt = 0; mt < 2; mt++)
#pragma unroll
        for (int nt = 0; nt < 8; nt++)
#pragma unroll
            for (int r = 0; r < 4; r++) acc[mt][nt][r] = 0.f;

    for (int k0 = 0; k0 < HC; k0 += 32) {
        __syncthreads();
#pragma unroll
        for (int u = 0; u < 4; u++) {
            const int e  = tid + 256 * u;
            const int r  = e >> 3;
            const int c4 = (e & 7) * 4;
            const size_t idx = (size_t)(m0 + r) * HC + k0 + c4;
            float4 va = *(const float4*)(g_o + idx);
            float4 vg = *(const float4*)(g_g + idx);
            va.x *= vg.x; va.y *= vg.y; va.z *= vg.z; va.w *= vg.w;
            uint32_t h0,l0,h1,l1,h2,l2,h3,l3;
            tfsplit(va.x, h0, l0); tfsplit(va.y, h1, l1);
            tfsplit(va.z, h2, l2); tfsplit(va.w, h3, l3);
            *(uint4*)(Ash + r * APAD + c4) = make_uint4(h0,h1,h2,h3);
            *(uint4*)(Asl + r * APAD + c4) = make_uint4(l0,l1,l2,l3);
        }
#pragma unroll
        for (int u = 0; u < 4; u++) {
            const int e  = tid + 256 * u;
            const int r  = e >> 5;
            const int c4 = (e & 31) * 4;
            float4 vb = *(const float4*)(wo + (size_t)(k0 + r) * ND + n0 + c4);
            uint32_t h0,l0,h1,l1,h2,l2,h3,l3;
            tfsplit(vb.x, h0, l0); tfsplit(vb.y, h1, l1);
            tfsplit(vb.z, h2, l2); tfsplit(vb.w, h3, l3);
            *(uint4*)(Bsh + r * BPAD + c4) = make_uint4(h0,h1,h2,h3);
            *(uint4*)(Bsl + r * BPAD + c4) = make_uint4(l0,l1,l2,l3);
        }
        __syncthreads();

#pragma unroll
        for (int kc = 0; kc < 4; kc++) {
            uint32_t ah[2][4], al[2][4];
#pragma unroll
            for (int mt = 0; mt < 2; mt++) {
                const int rb = wm * 32 + mt * 16 + gid;
                ah[mt][0] = __float_as_uint(Ash[(rb)     * APAD + kc * 8 + m4]);
                ah[mt][1] = __float_as_uint(Ash[(rb + 8) * APAD + kc * 8 + m4]);
                ah[mt][2] = __float_as_uint(Ash[(rb)     * APAD + kc * 8 + m4 + 4]);
                ah[mt][3] = __float_as_uint(Ash[(rb + 8) * APAD + kc * 8 + m4 + 4]);
                al[mt][0] = __float_as_uint(Asl[(rb)     * APAD + kc * 8 + m4]);
                al[mt][1] = __float_as_uint(Asl[(rb + 8) * APAD + kc * 8 + m4]);
                al[mt][2] = __float_as_uint(Asl[(rb)     * APAD + kc * 8 + m4 + 4]);
                al[mt][3] = __float_as_uint(Asl[(rb + 8) * APAD + kc * 8 + m4 + 4]);
            }
#pragma unroll
            for (int nt = 0; nt < 8; nt++) {
                const int cb = wn * 64 + nt * 8 + gid;
                uint32_t bh0 = __float_as_uint(Bsh[(kc * 8 + m4)     * BPAD + cb]);
                uint32_t bh1 = __float_as_uint(Bsh[(kc * 8 + m4 + 4) * BPAD + cb]);
                uint32_t bl0 = __float_as_uint(Bsl[(kc * 8 + m4)     * BPAD + cb]);
                uint32_t bl1 = __float_as_uint(Bsl[(kc * 8 + m4 + 4) * BPAD + cb]);
#pragma unroll
                for (int mt = 0; mt < 2; mt++) {
                    mma_tf32(acc[mt][nt], ah[mt][0], ah[mt][1], ah[mt][2], ah[mt][3], bh0, bh1);
                    mma_tf32(acc[mt][nt], ah[mt][0], ah[mt][1], ah[mt][2], ah[mt][3], bl0, bl1);
                    mma_tf32(acc[mt][nt], al[mt][0], al[mt][1], al[mt][2], al[mt][3], bh0, bh1);
                }
            }
        }
    }

#pragma unroll
    for (int mt = 0; mt < 2; mt++) {
#pragma unroll
        for (int rr = 0; rr < 2; rr++) {
            const int row = m0 + wm * 32 + mt * 16 + gid + rr * 8;
#pragma unroll
            for (int nt = 0; nt < 8; nt++) {
                const int n = n0 + wn * 64 + nt * 8 + 2 * m4;
                float v0 = acc[mt][nt][rr * 2 + 0] + bo[n];
                float v1 = acc[mt][nt][rr * 2 + 1] + bo[n + 1];
                *(float2*)(out + (size_t)row * ND + n) = make_float2(v0, v1);
            }
        }
    }
}

// ---------------------------------------------------------------------------
// Launch
// ---------------------------------------------------------------------------
extern "C" void kernel_launch(void* const* d_in, const int* in_sizes, int n_in,
                              void* d_out, int out_size)
{
    const float* q_x       = (const float*)d_in[0];
    const float* kv_x      = (const float*)d_in[1];
    const float* bias_mask = (const float*)d_in[2];
    const float* bias_pair = (const float*)d_in[3];
    const float* wq        = (const float*)d_in[4];
    const float* wk        = (const float*)d_in[5];
    const float* wv        = (const float*)d_in[6];
    const float* wg        = (const float*)d_in[7];
    const float* bg        = (const float*)d_in[8];
    const float* wo        = (const float*)d_in[9];
    const float* bo        = (const float*)d_in[10];
    float* out             = (float*)d_out;

    const int smem_gemm = 2 * (128 * APAD + 32 * BPAD) * (int)sizeof(float);
    const int smem_attn = (4 * 64 * KVPAD + 64 + 128 * PPAD) * (int)sizeof(float);

    // projections: q, k, v, gate
    {
        cudaFuncSetAttribute(proj_kernel, cudaFuncAttributeMaxDynamicSharedMemorySize, smem_gemm);
        dim3 grid(HC / 128, NM / 128, 4);
        proj_kernel<<<grid, 256, smem_gemm>>>(q_x, kv_x, wq, wk, wv, wg, bg);
    }
    // flash attention
    {
        cudaFuncSetAttribute(attn_kernel, cudaFuncAttributeMaxDynamicSharedMemorySize, smem_attn);
        dim3 grid(NQ / 128, NB * NH);
        attn_kernel<<<grid, 256, smem_attn>>>(bias_mask, bias_pair);
    }
    // gated output projection
    {
        cudaFuncSetAttribute(out_kernel, cudaFuncAttributeMaxDynamicSharedMemorySize, smem_gemm);
        dim3 grid(ND / 128, NM / 128);
        out_kernel<<<grid, 256, smem_gemm>>>(wo, bo, out);
    }
}

// round 5
// speedup vs baseline: 2.1819x; 1.3767x over previous
#include <cuda_runtime.h>
#include <cuda_bf16.h>
#include <math.h>
#include <stdint.h>

// Problem constants
#define NB 4
#define NQ 1024
#define NK 1024
#define ND 256
#define NH 8
#define NC 32
#define NM (NB*NQ)
#define HC (NH*NC)

// Packed word counts
#define QW 16              // words per row of packed q/k (32 channels / 2)

// Scratch (device globals)
__device__ uint32_t g_qph[NB*NH*NQ*QW];  // packed bf16-hi Q, [bh][q][cw]
__device__ uint32_t g_qpl[NB*NH*NQ*QW];
__device__ uint32_t g_kph[NB*NH*NK*QW];  // packed bf16-hi K
__device__ uint32_t g_kpl[NB*NH*NK*QW];
__device__ float    g_v[NB*NH*NK*NC];    // fp32 V [bh][kv][c]
__device__ float    g_g[NM*HC];          // sigmoid gate
__device__ float    g_o[NM*HC];          // attention output
__device__ uint32_t g_wph[5*256*128];    // packed weights [mat][n][kw]
__device__ uint32_t g_wpl[5*256*128];

// ---------------------------------------------------------------------------
// bf16 split helpers
// ---------------------------------------------------------------------------
__device__ __forceinline__ void bsplit2(float x0, float x1, uint32_t& h, uint32_t& l) {
    __nv_bfloat162 H = __floats2bfloat162_rn(x0, x1);   // low = x0
    float h0 = __low2float(H), h1 = __high2float(H);
    __nv_bfloat162 L = __floats2bfloat162_rn(x0 - h0, x1 - h1);
    h = *reinterpret_cast<uint32_t*>(&H);
    l = *reinterpret_cast<uint32_t*>(&L);
}
__device__ __forceinline__ void mma_bf16(float* d,
                                         uint32_t a0, uint32_t a1, uint32_t a2, uint32_t a3,
                                         uint32_t b0, uint32_t b1) {
    asm volatile(
        "mma.sync.aligned.m16n8k16.row.col.f32.bf16.bf16.f32 "
        "{%0,%1,%2,%3}, {%4,%5,%6,%7}, {%8,%9}, {%0,%1,%2,%3};\n"
        : "+f"(d[0]), "+f"(d[1]), "+f"(d[2]), "+f"(d[3])
        : "r"(a0), "r"(a1), "r"(a2), "r"(a3), "r"(b0), "r"(b1));
}

extern __shared__ float smp[];

// ---------------------------------------------------------------------------
// Kernel 0: pack weights into [n][k-pair] bf16 hi/lo words. grid=(128,5),256.
// ---------------------------------------------------------------------------
__global__ __launch_bounds__(256) void pack_w_kernel(
    const float* __restrict__ wq, const float* __restrict__ wk,
    const float* __restrict__ wv, const float* __restrict__ wg,
    const float* __restrict__ wo)
{
    const int mat = blockIdx.y;
    const float* W = (mat == 0) ? wq : (mat == 1) ? wk : (mat == 2) ? wv :
                     (mat == 3) ? wg : wo;
    const int id = blockIdx.x * 256 + threadIdx.x;   // 0..32767
    const int kw = id >> 8;
    const int n  = id & 255;
    float x0 = W[(2 * kw) * 256 + n];
    float x1 = W[(2 * kw + 1) * 256 + n];
    uint32_t h, l;
    bsplit2(x0, x1, h, l);
    g_wph[mat * 32768 + n * 128 + kw] = h;
    g_wpl[mat * 32768 + n * 128 + kw] = l;
}

// ---------------------------------------------------------------------------
// Kernel 1: projections, split-bf16. grid=(2, 32, 4), block=256, dyn smem.
// Block tile 128x128, k-step 32. mode: 0=q,1=k,2=v,3=gate
// ---------------------------------------------------------------------------
#define GST 20   // smem word stride for proj tiles (16 words + pad 4)

__global__ __launch_bounds__(256) void proj_kernel(
    const float* __restrict__ q_x, const float* __restrict__ kv_x,
    const float* __restrict__ bg)
{
    const int mode = blockIdx.z;
    const float* A = (mode == 1 || mode == 2) ? kv_x : q_x;
    const uint32_t* WPH = g_wph + mode * 32768;
    const uint32_t* WPL = g_wpl + mode * 32768;

    uint32_t* ah_s = (uint32_t*)smp;          // [128][GST]
    uint32_t* al_s = ah_s + 128 * GST;
    uint32_t* bh_s = al_s + 128 * GST;        // [128 n][GST]
    uint32_t* bl_s = bh_s + 128 * GST;

    const int tid  = threadIdx.x;
    const int lane = tid & 31;
    const int wid  = tid >> 5;
    const int gid  = lane >> 2;
    const int m4   = lane & 3;
    const int wm   = wid & 3;
    const int wn   = wid >> 2;
    const int m0   = blockIdx.y * 128;
    const int n0   = blockIdx.x * 128;

    float acc[2][8][4];
#pragma unroll
    for (int mt = 0; mt < 2; mt++)
#pragma unroll
        for (int nt = 0; nt < 8; nt++)
#pragma unroll
            for (int r = 0; r < 4; r++) acc[mt][nt][r] = 0.f;

    for (int k0 = 0; k0 < ND; k0 += 32) {
        __syncthreads();
        // A tile 128x32 fp32 -> packed hi/lo words [r][kw]
#pragma unroll
        for (int u = 0; u < 4; u++) {
            const int e  = tid + 256 * u;
            const int r  = e >> 3;
            const int kw = (e & 7) * 2;
            float4 va = *(const float4*)(A + (size_t)(m0 + r) * ND + k0 + kw * 2);
            uint32_t h0, l0, h1, l1;
            bsplit2(va.x, va.y, h0, l0);
            bsplit2(va.z, va.w, h1, l1);
            *(uint2*)(ah_s + r * GST + kw) = make_uint2(h0, h1);
            *(uint2*)(al_s + r * GST + kw) = make_uint2(l0, l1);
        }
        // B tile: straight word copy from pre-packed weights [n][kw]
#pragma unroll
        for (int u = 0; u < 2; u++) {
            const int e   = tid + 256 * u;      // 0..511 uint4 units
            const int nl  = e >> 2;
            const int kw4 = (e & 3) * 4;
            *(uint4*)(bh_s + nl * GST + kw4) =
                *(const uint4*)(WPH + (size_t)(n0 + nl) * 128 + (k0 >> 1) + kw4);
            *(uint4*)(bl_s + nl * GST + kw4) =
                *(const uint4*)(WPL + (size_t)(n0 + nl) * 128 + (k0 >> 1) + kw4);
        }
        __syncthreads();

#pragma unroll
        for (int kc = 0; kc < 2; kc++) {
            uint32_t ah[2][4], al[2][4];
#pragma unroll
            for (int mt = 0; mt < 2; mt++) {
                const int rb = wm * 32 + mt * 16 + gid;
                ah[mt][0] = ah_s[(rb)     * GST + kc * 8 + m4];
                ah[mt][1] = ah_s[(rb + 8) * GST + kc * 8 + m4];
                ah[mt][2] = ah_s[(rb)     * GST + kc * 8 + m4 + 4];
                ah[mt][3] = ah_s[(rb + 8) * GST + kc * 8 + m4 + 4];
                al[mt][0] = al_s[(rb)     * GST + kc * 8 + m4];
                al[mt][1] = al_s[(rb + 8) * GST + kc * 8 + m4];
                al[mt][2] = al_s[(rb)     * GST + kc * 8 + m4 + 4];
                al[mt][3] = al_s[(rb + 8) * GST + kc * 8 + m4 + 4];
            }
#pragma unroll
            for (int nt = 0; nt < 8; nt++) {
                const int cb = wn * 64 + nt * 8 + gid;
                uint32_t bh0 = bh_s[cb * GST + kc * 8 + m4];
                uint32_t bh1 = bh_s[cb * GST + kc * 8 + m4 + 4];
                uint32_t bl0 = bl_s[cb * GST + kc * 8 + m4];
                uint32_t bl1 = bl_s[cb * GST + kc * 8 + m4 + 4];
#pragma unroll
                for (int mt = 0; mt < 2; mt++) {
                    mma_bf16(acc[mt][nt], ah[mt][0], ah[mt][1], ah[mt][2], ah[mt][3], bh0, bh1);
                    mma_bf16(acc[mt][nt], ah[mt][0], ah[mt][1], ah[mt][2], ah[mt][3], bl0, bl1);
                    mma_bf16(acc[mt][nt], al[mt][0], al[mt][1], al[mt][2], al[mt][3], bh0, bh1);
                }
            }
        }
    }

    const float qscale = 0.17677669529663687f;  // 1/sqrt(32)
#pragma unroll
    for (int mt = 0; mt < 2; mt++) {
#pragma unroll
        for (int rr = 0; rr < 2; rr++) {
            const int row = m0 + wm * 32 + mt * 16 + gid + rr * 8;
            const int b   = row >> 10;
            const int l   = row & 1023;
#pragma unroll
            for (int nt = 0; nt < 8; nt++) {
                const int n  = n0 + wn * 64 + nt * 8 + 2 * m4;
                const int h  = n >> 5;
                const int c  = n & 31;
                float v0 = acc[mt][nt][rr * 2 + 0];
                float v1 = acc[mt][nt][rr * 2 + 1];
                if (mode == 0) {
                    uint32_t hw, lw;
                    bsplit2(v0 * qscale, v1 * qscale, hw, lw);
                    const size_t wi = (((size_t)b * NH + h) * NQ + l) * QW + (c >> 1);
                    g_qph[wi] = hw; g_qpl[wi] = lw;
                } else if (mode == 1) {
                    uint32_t hw, lw;
                    bsplit2(v0, v1, hw, lw);
                    const size_t wi = (((size_t)b * NH + h) * NK + l) * QW + (c >> 1);
                    g_kph[wi] = hw; g_kpl[wi] = lw;
                } else if (mode == 2) {
                    *(float2*)(g_v + ((((size_t)b * NH + h) * NK) + l) * NC + c) = make_float2(v0, v1);
                } else {
                    float s0 = 1.f / (1.f + __expf(-(v0 + bg[n])));
                    float s1 = 1.f / (1.f + __expf(-(v1 + bg[n + 1])));
                    *(float2*)(g_g + (size_t)row * HC + n) = make_float2(s0, s1);
                }
            }
        }
    }
}

// ---------------------------------------------------------------------------
// Kernel 2: flash attention, split-bf16. grid=(8, 32), block=256, dyn smem.
// Q-tile 128 (warp owns 16 full rows), K-tile 64, online softmax.
// ---------------------------------------------------------------------------
#define KST 20   // K tile: 64 rows x (16 words + pad 4)
#define VST 37   // V tile: 32 rows x (32 words + pad 5)
#define PST 36   // P tile: 128 rows x (32 words + pad 4)

__global__ __launch_bounds__(256) void attn_kernel(
    const float* __restrict__ bias_mask,   // [B, K]
    const float* __restrict__ bias_pair)   // [B, H, Q, K]
{
    uint32_t* kh = (uint32_t*)smp;          // [64][KST]
    uint32_t* kl = kh + 64 * KST;
    uint32_t* vh = kl + 64 * KST;           // [32][VST] (rows=channel, words=kv-pair)
    uint32_t* vl = vh + 32 * VST;
    uint32_t* ph = vl + 32 * VST;           // [128][PST]
    uint32_t* pl = ph + 128 * PST;
    float*    bms = (float*)(pl + 128 * PST);  // [64]

    const int tid  = threadIdx.x;
    const int lane = tid & 31;
    const int wid  = tid >> 5;
    const int gid  = lane >> 2;
    const int m4   = lane & 3;
    const int bh   = blockIdx.y;
    const int b    = bh >> 3;
    const int h    = bh & 7;
    const int q0   = blockIdx.x * 128;
    const int r0   = q0 + wid * 16 + gid;
    const int prow = wid * 16 + gid;

    // Q fragments (packed hi/lo words from gmem)
    uint32_t qh[2][4], ql[2][4];
    {
        const uint32_t* qbh = g_qph + (size_t)bh * NQ * QW;
        const uint32_t* qbl = g_qpl + (size_t)bh * NQ * QW;
#pragma unroll
        for (int kc = 0; kc < 2; kc++) {
            qh[kc][0] = qbh[(size_t)(r0)     * QW + kc * 8 + m4];
            qh[kc][1] = qbh[(size_t)(r0 + 8) * QW + kc * 8 + m4];
            qh[kc][2] = qbh[(size_t)(r0)     * QW + kc * 8 + m4 + 4];
            qh[kc][3] = qbh[(size_t)(r0 + 8) * QW + kc * 8 + m4 + 4];
            ql[kc][0] = qbl[(size_t)(r0)     * QW + kc * 8 + m4];
            ql[kc][1] = qbl[(size_t)(r0 + 8) * QW + kc * 8 + m4];
            ql[kc][2] = qbl[(size_t)(r0)     * QW + kc * 8 + m4 + 4];
            ql[kc][3] = qbl[(size_t)(r0 + 8) * QW + kc * 8 + m4 + 4];
        }
    }

    float m_i[2] = {-1e30f, -1e30f};
    float l_i[2] = {0.f, 0.f};
    float o[4][4];
#pragma unroll
    for (int nt = 0; nt < 4; nt++)
#pragma unroll
        for (int r = 0; r < 4; r++) o[nt][r] = 0.f;

    const uint32_t* kgh = g_kph + (size_t)bh * NK * QW;
    const uint32_t* kgl = g_kpl + (size_t)bh * NK * QW;
    const float*    vgb = g_v + (size_t)bh * NK * NC;
    const float*    bpb = bias_pair + ((size_t)bh * NQ + r0) * NK;
    const float*    bmb = bias_mask + (size_t)b * NK;

    for (int kt = 0; kt < 16; kt++) {
        __syncthreads();
        // K tile: straight word copy (uint4), 64 rows x 16 words
        {
            const int r   = tid >> 2;
            const int kw4 = (tid & 3) * 4;
            const size_t src = ((size_t)(kt * 64 + r)) * QW + kw4;
            *(uint4*)(kh + r * KST + kw4) = *(const uint4*)(kgh + src);
            *(uint4*)(kl + r * KST + kw4) = *(const uint4*)(kgl + src);
        }
        // V tile: fp32 -> kv-pair packed [c][r2]
        {
            const float* vg = vgb + (size_t)kt * 64 * NC;
#pragma unroll
            for (int u = 0; u < 4; u++) {
                const int w  = tid + 256 * u;      // 0..1023
                const int c  = w & 31;
                const int r2 = w >> 5;
                float x0 = vg[(2 * r2)     * NC + c];
                float x1 = vg[(2 * r2 + 1) * NC + c];
                uint32_t hw, lw;
                bsplit2(x0, x1, hw, lw);
                vh[c * VST + r2] = hw;
                vl[c * VST + r2] = lw;
            }
            if (tid < 64) bms[tid] = bmb[kt * 64 + tid];
        }
        __syncthreads();

        // S accumulators pre-loaded with biases
        float s[8][4];
        {
            const float* bp = bpb + kt * 64;
#pragma unroll
            for (int nt = 0; nt < 8; nt++) {
                const int c = nt * 8 + 2 * m4;
                const float bm0 = bms[c], bm1 = bms[c + 1];
                float2 p0 = *(const float2*)(bp + c);
                float2 p1 = *(const float2*)(bp + (size_t)8 * NK + c);
                s[nt][0] = p0.x + bm0; s[nt][1] = p0.y + bm1;
                s[nt][2] = p1.x + bm0; s[nt][3] = p1.y + bm1;
            }
        }
        // S += Q @ K^T (split-bf16: hh, hl, lh)
#pragma unroll
        for (int kc = 0; kc < 2; kc++) {
#pragma unroll
            for (int nt = 0; nt < 8; nt++) {
                const int cn = nt * 8 + gid;
                uint32_t bh0 = kh[cn * KST + kc * 8 + m4];
                uint32_t bh1 = kh[cn * KST + kc * 8 + m4 + 4];
                uint32_t bl0 = kl[cn * KST + kc * 8 + m4];
                uint32_t bl1 = kl[cn * KST + kc * 8 + m4 + 4];
                mma_bf16(s[nt], qh[kc][0], qh[kc][1], qh[kc][2], qh[kc][3], bh0, bh1);
                mma_bf16(s[nt], qh[kc][0], qh[kc][1], qh[kc][2], qh[kc][3], bl0, bl1);
                mma_bf16(s[nt], ql[kc][0], ql[kc][1], ql[kc][2], ql[kc][3], bh0, bh1);
            }
        }

        // online softmax (rows r0, r0+8); quad-local reduction
        float mx0 = -1e30f, mx1 = -1e30f;
#pragma unroll
        for (int nt = 0; nt < 8; nt++) {
            mx0 = fmaxf(mx0, fmaxf(s[nt][0], s[nt][1]));
            mx1 = fmaxf(mx1, fmaxf(s[nt][2], s[nt][3]));
        }
#pragma unroll
        for (int off = 1; off < 4; off <<= 1) {
            mx0 = fmaxf(mx0, __shfl_xor_sync(0xffffffffu, mx0, off));
            mx1 = fmaxf(mx1, __shfl_xor_sync(0xffffffffu, mx1, off));
        }
        const float mn0 = fmaxf(m_i[0], mx0);
        const float mn1 = fmaxf(m_i[1], mx1);
        const float al0 = __expf(m_i[0] - mn0);
        const float al1 = __expf(m_i[1] - mn1);
        float sum0 = 0.f, sum1 = 0.f;
#pragma unroll
        for (int nt = 0; nt < 8; nt++) {
            float e0 = __expf(s[nt][0] - mn0);
            float e1 = __expf(s[nt][1] - mn0);
            float e2 = __expf(s[nt][2] - mn1);
            float e3 = __expf(s[nt][3] - mn1);
            sum0 += e0 + e1;
            sum1 += e2 + e3;
            const int wi = nt * 4 + m4;
            uint32_t hw, lw;
            bsplit2(e0, e1, hw, lw);
            ph[(prow)     * PST + wi] = hw;
            pl[(prow)     * PST + wi] = lw;
            bsplit2(e2, e3, hw, lw);
            ph[(prow + 8) * PST + wi] = hw;
            pl[(prow + 8) * PST + wi] = lw;
        }
#pragma unroll
        for (int off = 1; off < 4; off <<= 1) {
            sum0 += __shfl_xor_sync(0xffffffffu, sum0, off);
            sum1 += __shfl_xor_sync(0xffffffffu, sum1, off);
        }
        l_i[0] = l_i[0] * al0 + sum0;
        l_i[1] = l_i[1] * al1 + sum1;
        m_i[0] = mn0; m_i[1] = mn1;
#pragma unroll
        for (int nt = 0; nt < 4; nt++) {
            o[nt][0] *= al0; o[nt][1] *= al0;
            o[nt][2] *= al1; o[nt][3] *= al1;
        }

        __syncwarp();
        // O += P @ V  (contraction 64 -> 4 chunks of k16)
#pragma unroll
        for (int kc = 0; kc < 4; kc++) {
            uint32_t a0h = ph[(prow)     * PST + kc * 8 + m4];
            uint32_t a1h = ph[(prow + 8) * PST + kc * 8 + m4];
            uint32_t a2h = ph[(prow)     * PST + kc * 8 + m4 + 4];
            uint32_t a3h = ph[(prow + 8) * PST + kc * 8 + m4 + 4];
            uint32_t a0l = pl[(prow)     * PST + kc * 8 + m4];
            uint32_t a1l = pl[(prow + 8) * PST + kc * 8 + m4];
            uint32_t a2l = pl[(prow)     * PST + kc * 8 + m4 + 4];
            uint32_t a3l = pl[(prow + 8) * PST + kc * 8 + m4 + 4];
#pragma unroll
            for (int nt = 0; nt < 4; nt++) {
                const int cn = nt * 8 + gid;
                uint32_t bh0 = vh[cn * VST + kc * 8 + m4];
                uint32_t bh1 = vh[cn * VST + kc * 8 + m4 + 4];
                uint32_t bl0 = vl[cn * VST + kc * 8 + m4];
                uint32_t bl1 = vl[cn * VST + kc * 8 + m4 + 4];
                mma_bf16(o[nt], a0h, a1h, a2h, a3h, bh0, bh1);
                mma_bf16(o[nt], a0h, a1h, a2h, a3h, bl0, bl1);
                mma_bf16(o[nt], a0l, a1l, a2l, a3l, bh0, bh1);
            }
        }
    }

    // epilogue: normalize, write [B, Q, H, C]
    const float inv0 = 1.f / l_i[0];
    const float inv1 = 1.f / l_i[1];
#pragma unroll
    for (int nt = 0; nt < 4; nt++) {
        const int c = nt * 8 + 2 * m4;
        *(float2*)(g_o + (((size_t)b * NQ + r0)     * NH + h) * NC + c) =
            make_float2(o[nt][0] * inv0, o[nt][1] * inv0);
        *(float2*)(g_o + (((size_t)b * NQ + r0 + 8) * NH + h) * NC + c) =
            make_float2(o[nt][2] * inv1, o[nt][3] * inv1);
    }
}

// ---------------------------------------------------------------------------
// Kernel 3: out = (o * g) @ wo + bo. grid=(2, 32), block=256, dyn smem.
// ---------------------------------------------------------------------------
__global__ __launch_bounds__(256) void out_kernel(
    const float* __restrict__ bo, float* __restrict__ out)
{
    const uint32_t* WPH = g_wph + 4 * 32768;
    const uint32_t* WPL = g_wpl + 4 * 32768;

    uint32_t* ah_s = (uint32_t*)smp;
    uint32_t* al_s = ah_s + 128 * GST;
    uint32_t* bh_s = al_s + 128 * GST;
    uint32_t* bl_s = bh_s + 128 * GST;

    const int tid  = threadIdx.x;
    const int lane = tid & 31;
    const int wid  = tid >> 5;
    const int gid  = lane >> 2;
    const int m4   = lane & 3;
    const int wm   = wid & 3;
    const int wn   = wid >> 2;
    const int m0   = blockIdx.y * 128;
    const int n0   = blockIdx.x * 128;

    float acc[2][8][4];
#pragma unroll
    for (int mt = 0; mt < 2; mt++)
#pragma unroll
        for (int nt = 0; nt < 8; nt++)
#pragma unroll
            for (int r = 0; r < 4; r++) acc[mt][nt][r] = 0.f;

    for (int k0 = 0; k0 < HC; k0 += 32) {
        __syncthreads();
#pragma unroll
        for (int u = 0; u < 4; u++) {
            const int e  = tid + 256 * u;
            const int r  = e >> 3;
            const int kw = (e & 7) * 2;
            const size_t idx = (size_t)(m0 + r) * HC + k0 + kw * 2;
            float4 va = *(const float4*)(g_o + idx);
            float4 vg = *(const float4*)(g_g + idx);
            va.x *= vg.x; va.y *= vg.y; va.z *= vg.z; va.w *= vg.w;
            uint32_t h0, l0, h1, l1;
            bsplit2(va.x, va.y, h0, l0);
            bsplit2(va.z, va.w, h1, l1);
            *(uint2*)(ah_s + r * GST + kw) = make_uint2(h0, h1);
            *(uint2*)(al_s + r * GST + kw) = make_uint2(l0, l1);
        }
#pragma unroll
        for (int u = 0; u < 2; u++) {
            const int e   = tid + 256 * u;
            const int nl  = e >> 2;
            const int kw4 = (e & 3) * 4;
            *(uint4*)(bh_s + nl * GST + kw4) =
                *(const uint4*)(WPH + (size_t)(n0 + nl) * 128 + (k0 >> 1) + kw4);
            *(uint4*)(bl_s + nl * GST + kw4) =
                *(const uint4*)(WPL + (size_t)(n0 + nl) * 128 + (k0 >> 1) + kw4);
        }
        __syncthreads();

#pragma unroll
        for (int kc = 0; kc < 2; kc++) {
            uint32_t ah[2][4], al[2][4];
#pragma unroll
            for (int mt = 0; mt < 2; mt++) {
                const int rb = wm * 32 + mt * 16 + gid;
                ah[mt][0] = ah_s[(rb)     * GST + kc * 8 + m4];
                ah[mt][1] = ah_s[(rb + 8) * GST + kc * 8 + m4];
                ah[mt][2] = ah_s[(rb)     * GST + kc * 8 + m4 + 4];
                ah[mt][3] = ah_s[(rb + 8) * GST + kc * 8 + m4 + 4];
                al[mt][0] = al_s[(rb)     * GST + kc * 8 + m4];
                al[mt][1] = al_s[(rb + 8) * GST + kc * 8 + m4];
                al[mt][2] = al_s[(rb)     * GST + kc * 8 + m4 + 4];
                al[mt][3] = al_s[(rb + 8) * GST + kc * 8 + m4 + 4];
            }
#pragma unroll
            for (int nt = 0; nt < 8; nt++) {
                const int cb = wn * 64 + nt * 8 + gid;
                uint32_t bh0 = bh_s[cb * GST + kc * 8 + m4];
                uint32_t bh1 = bh_s[cb * GST + kc * 8 + m4 + 4];
                uint32_t bl0 = bl_s[cb * GST + kc * 8 + m4];
                uint32_t bl1 = bl_s[cb * GST + kc * 8 + m4 + 4];
#pragma unroll
                for (int mt = 0; mt < 2; mt++) {
                    mma_bf16(acc[mt][nt], ah[mt][0], ah[mt][1], ah[mt][2], ah[mt][3], bh0, bh1);
                    mma_bf16(acc[mt][nt], ah[mt][0], ah[mt][1], ah[mt][2], ah[mt][3], bl0, bl1);
                    mma_bf16(acc[mt][nt], al[mt][0], al[mt][1], al[mt][2], al[mt][3], bh0, bh1);
                }
            }
        }
    }

#pragma unroll
    for (int mt = 0; mt < 2; mt++) {
#pragma unroll
        for (int rr = 0; rr < 2; rr++) {
            const int row = m0 + wm * 32 + mt * 16 + gid + rr * 8;
#pragma unroll
            for (int nt = 0; nt < 8; nt++) {
                const int n = n0 + wn * 64 + nt * 8 + 2 * m4;
                float v0 = acc[mt][nt][rr * 2 + 0] + bo[n];
                float v1 = acc[mt][nt][rr * 2 + 1] + bo[n + 1];
                *(float2*)(out + (size_t)row * ND + n) = make_float2(v0, v1);
            }
        }
    }
}

// ---------------------------------------------------------------------------
// Launch
// ---------------------------------------------------------------------------
extern "C" void kernel_launch(void* const* d_in, const int* in_sizes, int n_in,
                              void* d_out, int out_size)
{
    const float* q_x       = (const float*)d_in[0];
    const float* kv_x      = (const float*)d_in[1];
    const float* bias_mask = (const float*)d_in[2];
    const float* bias_pair = (const float*)d_in[3];
    const float* wq        = (const float*)d_in[4];
    const float* wk        = (const float*)d_in[5];
    const float* wv        = (const float*)d_in[6];
    const float* wg        = (const float*)d_in[7];
    const float* bg        = (const float*)d_in[8];
    const float* wo        = (const float*)d_in[9];
    const float* bo        = (const float*)d_in[10];
    float* out             = (float*)d_out;

    const int smem_gemm = 4 * 128 * GST * (int)sizeof(uint32_t);               // 40960
    const int smem_attn = (2 * 64 * KST + 2 * 32 * VST + 2 * 128 * PST + 64)
                          * (int)sizeof(uint32_t);                             // 56832

    // weight packing (cheap; runs inside the graph, deterministic)
    pack_w_kernel<<<dim3(128, 5), 256>>>(wq, wk, wv, wg, wo);

    // projections: q, k, v, gate
    {
        cudaFuncSetAttribute(proj_kernel, cudaFuncAttributeMaxDynamicSharedMemorySize, smem_gemm);
        dim3 grid(HC / 128, NM / 128, 4);
        proj_kernel<<<grid, 256, smem_gemm>>>(q_x, kv_x, bg);
    }
    // flash attention
    {
        cudaFuncSetAttribute(attn_kernel, cudaFuncAttributeMaxDynamicSharedMemorySize, smem_attn);
        dim3 grid(NQ / 128, NB * NH);
        attn_kernel<<<grid, 256, smem_attn>>>(bias_mask, bias_pair);
    }
    // gated output projection
    {
        cudaFuncSetAttribute(out_kernel, cudaFuncAttributeMaxDynamicSharedMemorySize, smem_gemm);
        dim3 grid(ND / 128, NM / 128);
        out_kernel<<<grid, 256, smem_gemm>>>(bo, out);
    }
}